// round 2
// baseline (speedup 1.0000x reference)
#include <cuda_runtime.h>

// Problem constants (fixed by the reference)
#define N_NODES 50000
#define N_EDGES 600000
#define C 128
#define H 256
#define EPS_GEN 1e-7f
#define EPS_BN  1e-5f

// ---------------- scratch (device globals; no allocation allowed) ----------
__device__ float g_h  [N_NODES * C];   // relu(BN(x))
__device__ float g_den[N_NODES * C];   // sum exp(msg)
__device__ float g_num[N_NODES * C];   // sum msg*exp(msg); later reused as MLP input
__device__ float g_y0 [N_NODES * H];
__device__ float g_y1 [N_NODES * H];
__device__ float g_t2 [N_NODES * C];   // x + conv_out
__device__ float g_sum[H];
__device__ float g_sumsq[H];
__device__ float g_scale[H];
__device__ float g_shift[H];

// ---------------- small utility kernels -----------------------------------
__global__ void zero_edge_buffers() {
    int i = blockIdx.x * blockDim.x + threadIdx.x;
    int stride = gridDim.x * blockDim.x;
    for (; i < N_NODES * C; i += stride) {
        g_den[i] = 0.f;
        g_num[i] = 0.f;
    }
}

__global__ void zero_stats() {
    int i = threadIdx.x;
    if (i < H) { g_sum[i] = 0.f; g_sumsq[i] = 0.f; }
}

// Column stats: blockDim.x == Ccols (128 or 256). Coalesced row reads.
__global__ void colstats(const float* __restrict__ A, int rows, int Ccols) {
    int c = threadIdx.x;
    float s = 0.f, sq = 0.f;
    for (int r = blockIdx.x; r < rows; r += gridDim.x) {
        float v = A[(size_t)r * Ccols + c];
        s += v;
        sq += v * v;
    }
    atomicAdd(&g_sum[c], s);
    atomicAdd(&g_sumsq[c], sq);
}

__global__ void finalize_stats(int Ccols, int rows,
                               const float* __restrict__ g,
                               const float* __restrict__ b) {
    int c = threadIdx.x;
    if (c < Ccols) {
        float mean = g_sum[c] / rows;
        float var  = g_sumsq[c] / rows - mean * mean;
        float rs   = rsqrtf(var + EPS_BN);
        float sc   = rs * g[c];
        g_scale[c] = sc;
        g_shift[c] = b[c] - mean * sc;
    }
}

// out = relu(A*scale + shift); A and O may alias (pure elementwise)
__global__ void bn_relu(const float* __restrict__ A, float* __restrict__ O,
                        int total, int cmask) {
    int i = blockIdx.x * blockDim.x + threadIdx.x;
    int stride = gridDim.x * blockDim.x;
    for (; i < total; i += stride) {
        int c = i & cmask;  // Ccols is a power of two
        float v = A[i] * g_scale[c] + g_shift[c];
        O[i] = fmaxf(v, 0.f);
    }
}

// ---------------- edge pass (single fused softmax-agg pass) ----------------
// One warp per edge: gather 128-float row of h[src], accumulate exp and
// msg*exp into den/num at dst via atomics. Segment-max skipped: softmax is
// shift-invariant and msg = relu(BN(x)) + eps is bounded, so exp never
// overflows; result is identical to the max-shifted form up to fp32 rounding.
__global__ void edge_pass(const int* __restrict__ ei,
                          const float* __restrict__ h) {
    int warp = (blockIdx.x * blockDim.x + threadIdx.x) >> 5;
    int lane = threadIdx.x & 31;
    int nwarp = (gridDim.x * blockDim.x) >> 5;
    for (int e = warp; e < N_EDGES; e += nwarp) {
        int s = __ldg(ei + e);
        int d = __ldg(ei + N_EDGES + e);
        float4 v = __ldg((const float4*)(h + (size_t)s * C) + lane);
        float m0 = fmaxf(v.x, 0.f) + EPS_GEN;
        float m1 = fmaxf(v.y, 0.f) + EPS_GEN;
        float m2 = fmaxf(v.z, 0.f) + EPS_GEN;
        float m3 = fmaxf(v.w, 0.f) + EPS_GEN;
        float e0 = __expf(m0);
        float e1 = __expf(m1);
        float e2 = __expf(m2);
        float e3 = __expf(m3);
        float* dp = g_den + (size_t)d * C + lane * 4;
        float* np = g_num + (size_t)d * C + lane * 4;
        atomicAdd(dp + 0, e0);
        atomicAdd(dp + 1, e1);
        atomicAdd(dp + 2, e2);
        atomicAdd(dp + 3, e3);
        atomicAdd(np + 0, m0 * e0);
        atomicAdd(np + 1, m1 * e1);
        atomicAdd(np + 2, m2 * e2);
        atomicAdd(np + 3, m3 * e3);
    }
}

// mlp_in (stored into g_num) = num/(den+1e-16) + h
__global__ void combine_agg() {
    int i = blockIdx.x * blockDim.x + threadIdx.x;
    int stride = gridDim.x * blockDim.x;
    for (; i < N_NODES * C; i += stride) {
        g_num[i] = g_num[i] / (g_den[i] + 1e-16f) + g_h[i];
    }
}

// ---------------- SGEMM: C[M,N] = A[M,K] @ B[K,N] + bias (+resid) ----------
#define BM 128
#define BN 128
#define BK 16
#define TM 8
#define TN 8

__global__ __launch_bounds__(256)
void sgemm(const float* __restrict__ A, const float* __restrict__ B,
           const float* __restrict__ bias, const float* __restrict__ resid,
           float* __restrict__ Cout, int M, int Ncols, int K) {
    __shared__ float As[BK][BM];
    __shared__ float Bs[BK][BN];

    int tid = threadIdx.x;
    int tc = tid & 15;   // 16 col-groups
    int tr = tid >> 4;   // 16 row-groups
    int rowBase = blockIdx.y * BM;
    int colBase = blockIdx.x * BN;

    float acc[TM][TN];
#pragma unroll
    for (int i = 0; i < TM; i++)
#pragma unroll
        for (int j = 0; j < TN; j++) acc[i][j] = 0.f;

    for (int k0 = 0; k0 < K; k0 += BK) {
        // A tile: BM x BK, float4 along K, stored transposed
#pragma unroll
        for (int i = tid; i < BM * BK / 4; i += 256) {
            int m = i >> 2, kq = i & 3;
            float4 v = make_float4(0.f, 0.f, 0.f, 0.f);
            int gr = rowBase + m;
            if (gr < M)
                v = *(const float4*)(A + (size_t)gr * K + k0 + kq * 4);
            As[kq * 4 + 0][m] = v.x;
            As[kq * 4 + 1][m] = v.y;
            As[kq * 4 + 2][m] = v.z;
            As[kq * 4 + 3][m] = v.w;
        }
        // B tile: BK x BN (Ncols always multiple of BN here)
#pragma unroll
        for (int i = tid; i < BK * BN / 4; i += 256) {
            int k = i >> 5, nq = i & 31;
            float4 v = *(const float4*)(B + (size_t)(k0 + k) * Ncols + colBase + nq * 4);
            *(float4*)&Bs[k][nq * 4] = v;
        }
        __syncthreads();

#pragma unroll
        for (int kk = 0; kk < BK; kk++) {
            float a[TM], b[TN];
#pragma unroll
            for (int i = 0; i < TM; i++) a[i] = As[kk][tr * TM + i];
#pragma unroll
            for (int j = 0; j < TN; j++) b[j] = Bs[kk][tc * TN + j];
#pragma unroll
            for (int i = 0; i < TM; i++)
#pragma unroll
                for (int j = 0; j < TN; j++) acc[i][j] += a[i] * b[j];
        }
        __syncthreads();
    }

#pragma unroll
    for (int i = 0; i < TM; i++) {
        int row = rowBase + tr * TM + i;
        if (row >= M) continue;
#pragma unroll
        for (int j = 0; j < TN; j++) {
            int col = colBase + tc * TN + j;
            float v = acc[i][j] + bias[col];
            if (resid) v += resid[(size_t)row * Ncols + col];
            Cout[(size_t)row * Ncols + col] = v;
        }
    }
}

// ---------------- launch ----------------------------------------------------
extern "C" void kernel_launch(void* const* d_in, const int* in_sizes, int n_in,
                              void* d_out, int out_size) {
    const float* x    = (const float*)d_in[0];
    const int*   ei   = (const int*)d_in[1];   // int32! (JAX x64 disabled)
    const float* bn_g = (const float*)d_in[2];
    const float* bn_b = (const float*)d_in[3];
    const float* W1   = (const float*)d_in[4];
    const float* b1   = (const float*)d_in[5];
    const float* g1   = (const float*)d_in[6];
    const float* be1  = (const float*)d_in[7];
    const float* W2   = (const float*)d_in[8];
    const float* b2   = (const float*)d_in[9];
    const float* g2   = (const float*)d_in[10];
    const float* be2  = (const float*)d_in[11];
    const float* W3   = (const float*)d_in[12];
    const float* b3   = (const float*)d_in[13];
    const float* We   = (const float*)d_in[14];
    const float* be   = (const float*)d_in[15];
    float* out = (float*)d_out;

    float* p_h;   cudaGetSymbolAddress((void**)&p_h,   g_h);
    float* p_num; cudaGetSymbolAddress((void**)&p_num, g_num);
    float* p_y0;  cudaGetSymbolAddress((void**)&p_y0,  g_y0);
    float* p_y1;  cudaGetSymbolAddress((void**)&p_y1,  g_y1);
    float* p_t2;  cudaGetSymbolAddress((void**)&p_t2,  g_t2);

    const int EW = 256;  // elementwise block
    int nNC = N_NODES * C;
    int nNH = N_NODES * H;

    // 1) zero accumulators
    zero_edge_buffers<<<4096, EW>>>();

    // 2) BN(x) stats -> h = relu(BN(x))
    zero_stats<<<1, H>>>();
    colstats<<<512, C>>>(x, N_NODES, C);
    finalize_stats<<<1, C>>>(C, N_NODES, bn_g, bn_b);
    bn_relu<<<(nNC + EW - 1) / EW, EW>>>(x, p_h, nNC, C - 1);

    // 3) fused softmax-aggregation edge pass (1 warp / edge)
    edge_pass<<<(N_EDGES * 32 + EW - 1) / EW, EW>>>(ei, p_h);

    // 4) mlp_in = agg + h   (into g_num)
    combine_agg<<<(nNC + EW - 1) / EW, EW>>>();

    // 5) MLP layer 1: y0 = mlp_in @ W1 + b1 ; BN ; relu
    sgemm<<<dim3(H / BN, (N_NODES + BM - 1) / BM), 256>>>(
        p_num, W1, b1, nullptr, p_y0, N_NODES, H, C);
    zero_stats<<<1, H>>>();
    colstats<<<512, H>>>(p_y0, N_NODES, H);
    finalize_stats<<<1, H>>>(H, N_NODES, g1, be1);
    bn_relu<<<(nNH + EW - 1) / EW, EW>>>(p_y0, p_y0, nNH, H - 1);

    // 6) MLP layer 2: y1 = y0 @ W2 + b2 ; BN ; relu
    sgemm<<<dim3(H / BN, (N_NODES + BM - 1) / BM), 256>>>(
        p_y0, W2, b2, nullptr, p_y1, N_NODES, H, H);
    zero_stats<<<1, H>>>();
    colstats<<<512, H>>>(p_y1, N_NODES, H);
    finalize_stats<<<1, H>>>(H, N_NODES, g2, be2);
    bn_relu<<<(nNH + EW - 1) / EW, EW>>>(p_y1, p_y1, nNH, H - 1);

    // 7) t2 = x + (y1 @ W3 + b3)
    sgemm<<<dim3(C / BN, (N_NODES + BM - 1) / BM), 256>>>(
        p_y1, W3, b3, x, p_t2, N_NODES, C, H);

    // 8) out = t2 @ We + be
    sgemm<<<dim3(C / BN, (N_NODES + BM - 1) / BM), 256>>>(
        p_t2, We, be, nullptr, out, N_NODES, C, C);
}

// round 6
// speedup vs baseline: 1.7773x; 1.7773x over previous
#include <cuda_runtime.h>
#include <cstdint>

// Problem constants (fixed by the reference)
#define N_NODES 50000
#define N_EDGES 600000
#define C 128
#define H 256
#define EPS_GEN 1e-7f
#define EPS_BN  1e-5f

// ---------------- scratch (device globals; no allocation allowed) ----------
__device__ float g_h  [N_NODES * C];   // relu(BN(x))
__device__ float g_min[N_NODES * C];   // mlp input = agg + h
__device__ float g_y0 [N_NODES * H];
__device__ float g_y1 [N_NODES * H];
__device__ float g_t2 [N_NODES * C];   // x + conv_out
__device__ float g_sum[H];
__device__ float g_sumsq[H];
__device__ float g_scale[H];
__device__ float g_shift[H];

// CSR-by-dst scratch
#define SCAN_B 512
#define NSCAN ((N_NODES + SCAN_B - 1) / SCAN_B)
__device__ int g_cnt [N_NODES];
__device__ int g_cur [N_NODES];
__device__ int g_off [N_NODES + 1];
__device__ int g_bsum[NSCAN];
__device__ int g_srcs[N_EDGES];

// ---------------- small utility kernels -----------------------------------
__global__ void zero_stats() {
    int i = threadIdx.x;
    if (i < H) { g_sum[i] = 0.f; g_sumsq[i] = 0.f; }
}

// Column stats for the input-x BN: blockDim.x == Ccols.
__global__ void colstats(const float* __restrict__ A, int rows, int Ccols) {
    int c = threadIdx.x;
    float s = 0.f, sq = 0.f;
    for (int r = blockIdx.x; r < rows; r += gridDim.x) {
        float v = A[(size_t)r * Ccols + c];
        s += v;
        sq += v * v;
    }
    atomicAdd(&g_sum[c], s);
    atomicAdd(&g_sumsq[c], sq);
}

__global__ void finalize_stats(int Ccols, int rows,
                               const float* __restrict__ g,
                               const float* __restrict__ b) {
    int c = threadIdx.x;
    if (c < Ccols) {
        float mean = g_sum[c] / rows;
        float var  = g_sumsq[c] / rows - mean * mean;
        float rs   = rsqrtf(var + EPS_BN);
        float sc   = rs * g[c];
        g_scale[c] = sc;
        g_shift[c] = b[c] - mean * sc;
    }
}

// h = relu(x*scale + shift)
__global__ void bn_relu(const float* __restrict__ A, float* __restrict__ O,
                        int total, int cmask) {
    int i = blockIdx.x * blockDim.x + threadIdx.x;
    int stride = gridDim.x * blockDim.x;
    for (; i < total; i += stride) {
        int c = i & cmask;
        float v = A[i] * g_scale[c] + g_shift[c];
        O[i] = fmaxf(v, 0.f);
    }
}

// ---------------- CSR build (counting sort by dst) -------------------------
__global__ void zero_cnt() {
    int i = blockIdx.x * blockDim.x + threadIdx.x;
    if (i < N_NODES) g_cnt[i] = 0;
}

__global__ void hist(const int* __restrict__ ei) {
    int e = blockIdx.x * blockDim.x + threadIdx.x;
    if (e < N_EDGES) atomicAdd(&g_cnt[ei[N_EDGES + e]], 1);
}

__global__ void scan_sums() {
    __shared__ int sh[SCAN_B];
    int gi = blockIdx.x * SCAN_B + threadIdx.x;
    sh[threadIdx.x] = (gi < N_NODES) ? g_cnt[gi] : 0;
    __syncthreads();
    for (int ofs = SCAN_B / 2; ofs > 0; ofs >>= 1) {
        if (threadIdx.x < ofs) sh[threadIdx.x] += sh[threadIdx.x + ofs];
        __syncthreads();
    }
    if (threadIdx.x == 0) g_bsum[blockIdx.x] = sh[0];
}

__global__ void scan_bsum() {
    __shared__ int sh[NSCAN];
    int t = threadIdx.x;
    if (t < NSCAN) sh[t] = g_bsum[t];
    __syncthreads();
    if (t == 0) {
        int run = 0;
        for (int i = 0; i < NSCAN; i++) { int v = sh[i]; sh[i] = run; run += v; }
        g_off[N_NODES] = run;
    }
    __syncthreads();
    if (t < NSCAN) g_bsum[t] = sh[t];
}

__global__ void scan_final() {
    __shared__ int sh[2][SCAN_B];
    int b = blockIdx.x, t = threadIdx.x;
    int gi = b * SCAN_B + t;
    int v = (gi < N_NODES) ? g_cnt[gi] : 0;
    sh[0][t] = v;
    __syncthreads();
    int src = 0;
    for (int ofs = 1; ofs < SCAN_B; ofs <<= 1) {
        int nv = sh[src][t] + ((t >= ofs) ? sh[src][t - ofs] : 0);
        sh[src ^ 1][t] = nv;
        __syncthreads();
        src ^= 1;
    }
    int excl = sh[src][t] - v;  // exclusive scan
    if (gi < N_NODES) {
        int o = g_bsum[b] + excl;
        g_off[gi] = o;
        g_cur[gi] = o;
    }
}

__global__ void scatter(const int* __restrict__ ei) {
    int e = blockIdx.x * blockDim.x + threadIdx.x;
    if (e < N_EDGES) {
        int d = ei[N_EDGES + e];
        int p = atomicAdd(&g_cur[d], 1);
        g_srcs[p] = ei[e];
    }
}

// ---------------- aggregation: warp per dst node, zero atomics -------------
// softmax agg without segment-max: msg = h[src]+eps is >=0 and bounded, so
// exp never overflows; shift-invariance makes this identical up to rounding.
// Writes mlp_in = num/den + h[dst] directly.
__global__ void agg_kernel(const float* __restrict__ h, float* __restrict__ om) {
    int warp = (blockIdx.x * blockDim.x + threadIdx.x) >> 5;
    int lane = threadIdx.x & 31;
    if (warp >= N_NODES) return;
    int j0 = g_off[warp], j1 = g_off[warp + 1];
    float4 den = make_float4(0.f, 0.f, 0.f, 0.f);
    float4 num = make_float4(0.f, 0.f, 0.f, 0.f);
    for (int j = j0; j < j1; j++) {
        int s = g_srcs[j];
        float4 v = __ldg((const float4*)(h + (size_t)s * C) + lane);
        float m0 = v.x + EPS_GEN, m1 = v.y + EPS_GEN;
        float m2 = v.z + EPS_GEN, m3 = v.w + EPS_GEN;
        float e0 = __expf(m0), e1 = __expf(m1);
        float e2 = __expf(m2), e3 = __expf(m3);
        den.x += e0; den.y += e1; den.z += e2; den.w += e3;
        num.x += m0 * e0; num.y += m1 * e1; num.z += m2 * e2; num.w += m3 * e3;
    }
    float4 hd = ((const float4*)(h + (size_t)warp * C))[lane];
    float4 o;
    o.x = num.x / (den.x + 1e-16f) + hd.x;
    o.y = num.y / (den.y + 1e-16f) + hd.y;
    o.z = num.z / (den.z + 1e-16f) + hd.z;
    o.w = num.w / (den.w + 1e-16f) + hd.w;
    ((float4*)(om + (size_t)warp * C))[lane] = o;
}

// ---------------- tf32 tensor-core GEMM ------------------------------------
// C[M,N] = op(A)[M,K] @ B[K,N] + bias (+resid)
// PRE:   apply per-k-column scale/shift + relu to A while loading (fused BN)
// STATS: accumulate per-column sum/sumsq of output (fused BN stats)
__device__ __forceinline__ unsigned f2tf32(float v) {
    unsigned u;
    asm("cvt.rna.tf32.f32 %0, %1;" : "=r"(u) : "f"(v));
    return u;
}

template <bool PRE, bool STATS, bool RESID>
__global__ __launch_bounds__(256)
void gemm_tc(const float* __restrict__ A, const float* __restrict__ B,
             const float* __restrict__ bias, const float* __restrict__ resid,
             float* __restrict__ Cout, int M, int Ncols, int K) {
    __shared__ unsigned As[16][136];  // [k][m], pad 8 -> conflict-free frags
    __shared__ unsigned Bs[16][136];  // [k][n]
    __shared__ float smS[128], smQ[128];

    int tid = threadIdx.x;
    int warpId = tid >> 5, lane = tid & 31;
    int grp = lane >> 2, tig = lane & 3;
    int wm = (warpId >> 2) * 64;   // warp M offset (2 rows of warps)
    int wn = (warpId & 3) * 32;    // warp N offset (4 cols of warps)
    int rowBase = blockIdx.y * 128;
    int colBase = blockIdx.x * 128;

    float acc[4][4][4];
#pragma unroll
    for (int i = 0; i < 4; i++)
#pragma unroll
        for (int j = 0; j < 4; j++)
#pragma unroll
            for (int r = 0; r < 4; r++) acc[i][j][r] = 0.f;

    for (int k0 = 0; k0 < K; k0 += 16) {
        // A tile: 128 x 16, stored transposed [k][m]
#pragma unroll
        for (int i = tid; i < 512; i += 256) {
            int m = i >> 2, kq = i & 3;
            int row = rowBase + m;
            float4 v = make_float4(0.f, 0.f, 0.f, 0.f);
            if (row < M) v = *(const float4*)(A + (size_t)row * K + k0 + kq * 4);
            int kk = kq * 4;
            if (PRE) {
                v.x = fmaxf(v.x * g_scale[k0 + kk + 0] + g_shift[k0 + kk + 0], 0.f);
                v.y = fmaxf(v.y * g_scale[k0 + kk + 1] + g_shift[k0 + kk + 1], 0.f);
                v.z = fmaxf(v.z * g_scale[k0 + kk + 2] + g_shift[k0 + kk + 2], 0.f);
                v.w = fmaxf(v.w * g_scale[k0 + kk + 3] + g_shift[k0 + kk + 3], 0.f);
            }
            As[kk + 0][m] = f2tf32(v.x);
            As[kk + 1][m] = f2tf32(v.y);
            As[kk + 2][m] = f2tf32(v.z);
            As[kk + 3][m] = f2tf32(v.w);
        }
        // B tile: 16 x 128
#pragma unroll
        for (int i = tid; i < 512; i += 256) {
            int k = i >> 5, nq = i & 31;
            float4 v = *(const float4*)(B + (size_t)(k0 + k) * Ncols + colBase + nq * 4);
            Bs[k][nq * 4 + 0] = f2tf32(v.x);
            Bs[k][nq * 4 + 1] = f2tf32(v.y);
            Bs[k][nq * 4 + 2] = f2tf32(v.z);
            Bs[k][nq * 4 + 3] = f2tf32(v.w);
        }
        __syncthreads();

#pragma unroll
        for (int ks = 0; ks < 16; ks += 8) {
            unsigned a[4][4], b[4][2];
#pragma unroll
            for (int i = 0; i < 4; i++) {
                int r0 = wm + 16 * i + grp;
                a[i][0] = As[ks + tig][r0];
                a[i][1] = As[ks + tig][r0 + 8];
                a[i][2] = As[ks + tig + 4][r0];
                a[i][3] = As[ks + tig + 4][r0 + 8];
            }
#pragma unroll
            for (int j = 0; j < 4; j++) {
                int cn = wn + 8 * j + grp;
                b[j][0] = Bs[ks + tig][cn];
                b[j][1] = Bs[ks + tig + 4][cn];
            }
#pragma unroll
            for (int i = 0; i < 4; i++)
#pragma unroll
                for (int j = 0; j < 4; j++)
                    asm volatile(
                        "mma.sync.aligned.m16n8k8.row.col.f32.tf32.tf32.f32 "
                        "{%0,%1,%2,%3}, {%4,%5,%6,%7}, {%8,%9}, {%0,%1,%2,%3};"
                        : "+f"(acc[i][j][0]), "+f"(acc[i][j][1]),
                          "+f"(acc[i][j][2]), "+f"(acc[i][j][3])
                        : "r"(a[i][0]), "r"(a[i][1]), "r"(a[i][2]), "r"(a[i][3]),
                          "r"(b[j][0]), "r"(b[j][1]));
        }
        __syncthreads();
    }

    if (STATS) {
        if (tid < 128) { smS[tid] = 0.f; smQ[tid] = 0.f; }
        __syncthreads();
    }

#pragma unroll
    for (int j = 0; j < 4; j++) {
        int colL = wn + 8 * j + 2 * tig;
        int col = colBase + colL;
        float b0 = bias[col], b1 = bias[col + 1];
        float s0 = 0.f, q0 = 0.f, s1 = 0.f, q1 = 0.f;
#pragma unroll
        for (int i = 0; i < 4; i++) {
            int r0 = rowBase + wm + 16 * i + grp;
            int r1 = r0 + 8;
            if (r0 < M) {
                float v0 = acc[i][j][0] + b0;
                float v1 = acc[i][j][1] + b1;
                if (RESID) {
                    float2 rv = *(const float2*)(resid + (size_t)r0 * Ncols + col);
                    v0 += rv.x; v1 += rv.y;
                }
                *(float2*)(Cout + (size_t)r0 * Ncols + col) = make_float2(v0, v1);
                s0 += v0; q0 += v0 * v0; s1 += v1; q1 += v1 * v1;
            }
            if (r1 < M) {
                float v0 = acc[i][j][2] + b0;
                float v1 = acc[i][j][3] + b1;
                if (RESID) {
                    float2 rv = *(const float2*)(resid + (size_t)r1 * Ncols + col);
                    v0 += rv.x; v1 += rv.y;
                }
                *(float2*)(Cout + (size_t)r1 * Ncols + col) = make_float2(v0, v1);
                s0 += v0; q0 += v0 * v0; s1 += v1; q1 += v1 * v1;
            }
        }
        if (STATS) {
            atomicAdd(&smS[colL], s0);
            atomicAdd(&smQ[colL], q0);
            atomicAdd(&smS[colL + 1], s1);
            atomicAdd(&smQ[colL + 1], q1);
        }
    }
    if (STATS) {
        __syncthreads();
        if (tid < 128) {
            atomicAdd(&g_sum[colBase + tid], smS[tid]);
            atomicAdd(&g_sumsq[colBase + tid], smQ[tid]);
        }
    }
}

// ---------------- launch ----------------------------------------------------
extern "C" void kernel_launch(void* const* d_in, const int* in_sizes, int n_in,
                              void* d_out, int out_size) {
    const float* x    = (const float*)d_in[0];
    const int*   ei   = (const int*)d_in[1];   // int32 (JAX x64 disabled)
    const float* bn_g = (const float*)d_in[2];
    const float* bn_b = (const float*)d_in[3];
    const float* W1   = (const float*)d_in[4];
    const float* b1   = (const float*)d_in[5];
    const float* g1   = (const float*)d_in[6];
    const float* be1  = (const float*)d_in[7];
    const float* W2   = (const float*)d_in[8];
    const float* b2   = (const float*)d_in[9];
    const float* g2   = (const float*)d_in[10];
    const float* be2  = (const float*)d_in[11];
    const float* W3   = (const float*)d_in[12];
    const float* b3   = (const float*)d_in[13];
    const float* We   = (const float*)d_in[14];
    const float* be   = (const float*)d_in[15];
    float* out = (float*)d_out;

    float* p_h;   cudaGetSymbolAddress((void**)&p_h,   g_h);
    float* p_min; cudaGetSymbolAddress((void**)&p_min, g_min);
    float* p_y0;  cudaGetSymbolAddress((void**)&p_y0,  g_y0);
    float* p_y1;  cudaGetSymbolAddress((void**)&p_y1,  g_y1);
    float* p_t2;  cudaGetSymbolAddress((void**)&p_t2,  g_t2);

    const int EW = 256;
    int nNC = N_NODES * C;
    dim3 gemmGridH(2, (N_NODES + 127) / 128);   // N = 256
    dim3 gemmGridC(1, (N_NODES + 127) / 128);   // N = 128

    // --- BN(x) -> h ---
    zero_stats<<<1, H>>>();
    colstats<<<512, C>>>(x, N_NODES, C);
    finalize_stats<<<1, C>>>(C, N_NODES, bn_g, bn_b);
    bn_relu<<<(nNC + EW - 1) / EW, EW>>>(x, p_h, nNC, C - 1);

    // --- build dst-CSR (counting sort) ---
    zero_cnt<<<(N_NODES + EW - 1) / EW, EW>>>();
    hist<<<(N_EDGES + EW - 1) / EW, EW>>>(ei);
    scan_sums<<<NSCAN, SCAN_B>>>();
    scan_bsum<<<1, 128>>>();
    scan_final<<<NSCAN, SCAN_B>>>();
    scatter<<<(N_EDGES + EW - 1) / EW, EW>>>(ei);

    // --- softmax aggregation + root add (warp per node) ---
    agg_kernel<<<N_NODES / 8, 256>>>(p_h, p_min);

    // --- MLP layer 1: y0 = mlp_in @ W1 + b1 (stats fused) ---
    zero_stats<<<1, H>>>();
    gemm_tc<false, true, false><<<gemmGridH, 256>>>(
        p_min, W1, b1, nullptr, p_y0, N_NODES, H, C);
    finalize_stats<<<1, H>>>(H, N_NODES, g1, be1);

    // --- MLP layer 2: y1 = relu(BN(y0)) @ W2 + b2 (pre + stats fused) ---
    zero_stats<<<1, H>>>();
    gemm_tc<true, true, false><<<gemmGridH, 256>>>(
        p_y0, W2, b2, nullptr, p_y1, N_NODES, H, H);
    finalize_stats<<<1, H>>>(H, N_NODES, g2, be2);

    // --- MLP layer 3 + residual: t2 = x + relu(BN(y1)) @ W3 + b3 ---
    gemm_tc<true, false, true><<<gemmGridC, 256>>>(
        p_y1, W3, b3, x, p_t2, N_NODES, C, H);

    // --- encoder: out = t2 @ We + be ---
    gemm_tc<false, false, false><<<gemmGridC, 256>>>(
        p_t2, We, be, nullptr, out, N_NODES, C, C);
}

// round 8
// speedup vs baseline: 2.9220x; 1.6441x over previous
#include <cuda_runtime.h>
#include <cstdint>

// Problem constants (fixed by the reference)
#define N_NODES 50000
#define N_EDGES 600000
#define C 128
#define H 256
#define EPS_GEN 1e-7f
#define EPS_BN  1e-5f

// ---------------- scratch (device globals; no allocation allowed) ----------
__device__ float g_h  [N_NODES * C];   // relu(BN(x))
__device__ float g_min[N_NODES * C];   // mlp input = agg + h
__device__ float g_y0 [N_NODES * H];
__device__ float g_y1 [N_NODES * H];
__device__ float g_sum[H];
__device__ float g_sumsq[H];
__device__ float g_scale[H];
__device__ float g_shift[H];
__device__ float g_wc [384 * 128];     // [W3@We ; We]  (combined layer3+encoder)
__device__ float g_bc [128];           // b3@We + be

// CSR-by-dst scratch
#define SCAN_B 512
#define NSCAN ((N_NODES + SCAN_B - 1) / SCAN_B)
__device__ int g_cnt [N_NODES];
__device__ int g_cur [N_NODES];
__device__ int g_off [N_NODES + 1];
__device__ int g_bsum[NSCAN];
__device__ int g_srcs[N_EDGES];

// ---------------- small utility kernels -----------------------------------
__global__ void zero_stats() {
    int i = threadIdx.x;
    if (i < H) { g_sum[i] = 0.f; g_sumsq[i] = 0.f; }
}

// Column stats for the input-x BN: blockDim.x == Ccols.
__global__ void colstats(const float* __restrict__ A, int rows, int Ccols) {
    int c = threadIdx.x;
    float s = 0.f, sq = 0.f;
    for (int r = blockIdx.x; r < rows; r += gridDim.x) {
        float v = A[(size_t)r * Ccols + c];
        s += v;
        sq += v * v;
    }
    atomicAdd(&g_sum[c], s);
    atomicAdd(&g_sumsq[c], sq);
}

__global__ void finalize_stats(int Ccols, int rows,
                               const float* __restrict__ g,
                               const float* __restrict__ b) {
    int c = threadIdx.x;
    if (c < Ccols) {
        float mean = g_sum[c] / rows;
        float var  = g_sumsq[c] / rows - mean * mean;
        float rs   = rsqrtf(var + EPS_BN);
        float sc   = rs * g[c];
        g_scale[c] = sc;
        g_shift[c] = b[c] - mean * sc;
    }
}

// h = relu(x*scale + shift), float4-vectorized (4 elems/thread)
__global__ void bn_relu4(const float* __restrict__ A, float* __restrict__ O,
                         int total4, int cmask4) {
    int i = blockIdx.x * blockDim.x + threadIdx.x;
    int stride = gridDim.x * blockDim.x;
    for (; i < total4; i += stride) {
        int c4 = (i & cmask4) * 4;
        float4 v  = ((const float4*)A)[i];
        float4 sc = *(const float4*)&g_scale[c4];
        float4 sh = *(const float4*)&g_shift[c4];
        float4 o;
        o.x = fmaxf(fmaf(v.x, sc.x, sh.x), 0.f);
        o.y = fmaxf(fmaf(v.y, sc.y, sh.y), 0.f);
        o.z = fmaxf(fmaf(v.z, sc.z, sh.z), 0.f);
        o.w = fmaxf(fmaf(v.w, sc.w, sh.w), 0.f);
        ((float4*)O)[i] = o;
    }
}

// ---------------- combined-weight prep (layer3 @ encoder) -------------------
// g_wc rows 0..255 = W3 @ We ; rows 256..383 = We (filled via memcpyAsync)
__global__ void build_wc(const float* __restrict__ W3,
                         const float* __restrict__ We) {
    __shared__ float row[128];
    int k = blockIdx.x;       // 0..255
    int c = threadIdx.x;      // 0..127
    row[c] = W3[k * 128 + c];
    __syncthreads();
    float s = 0.f;
#pragma unroll 8
    for (int j = 0; j < 128; j++) s = fmaf(row[j], We[j * 128 + c], s);
    g_wc[k * 128 + c] = s;
}

// bc = b3 @ We + be   (b3 is length C=128: the layer-3 output bias)
__global__ void build_bc(const float* __restrict__ b3,
                         const float* __restrict__ We,
                         const float* __restrict__ be) {
    __shared__ float row[128];
    int c = threadIdx.x;      // 0..127
    row[c] = b3[c];
    __syncthreads();
    float s = be[c];
#pragma unroll 8
    for (int j = 0; j < 128; j++) s = fmaf(row[j], We[j * 128 + c], s);
    g_bc[c] = s;
}

// ---------------- CSR build (counting sort by dst) -------------------------
__global__ void zero_cnt() {
    int i = blockIdx.x * blockDim.x + threadIdx.x;
    if (i < N_NODES) g_cnt[i] = 0;
}

__global__ void hist(const int* __restrict__ ei) {
    int e = blockIdx.x * blockDim.x + threadIdx.x;
    if (e < N_EDGES) atomicAdd(&g_cnt[ei[N_EDGES + e]], 1);
}

__global__ void scan_sums() {
    __shared__ int sh[SCAN_B];
    int gi = blockIdx.x * SCAN_B + threadIdx.x;
    sh[threadIdx.x] = (gi < N_NODES) ? g_cnt[gi] : 0;
    __syncthreads();
    for (int ofs = SCAN_B / 2; ofs > 0; ofs >>= 1) {
        if (threadIdx.x < ofs) sh[threadIdx.x] += sh[threadIdx.x + ofs];
        __syncthreads();
    }
    if (threadIdx.x == 0) g_bsum[blockIdx.x] = sh[0];
}

__global__ void scan_bsum() {
    __shared__ int sh[NSCAN];
    int t = threadIdx.x;
    if (t < NSCAN) sh[t] = g_bsum[t];
    __syncthreads();
    if (t == 0) {
        int run = 0;
        for (int i = 0; i < NSCAN; i++) { int v = sh[i]; sh[i] = run; run += v; }
        g_off[N_NODES] = run;
    }
    __syncthreads();
    if (t < NSCAN) g_bsum[t] = sh[t];
}

__global__ void scan_final() {
    __shared__ int sh[2][SCAN_B];
    int b = blockIdx.x, t = threadIdx.x;
    int gi = b * SCAN_B + t;
    int v = (gi < N_NODES) ? g_cnt[gi] : 0;
    sh[0][t] = v;
    __syncthreads();
    int src = 0;
    for (int ofs = 1; ofs < SCAN_B; ofs <<= 1) {
        int nv = sh[src][t] + ((t >= ofs) ? sh[src][t - ofs] : 0);
        sh[src ^ 1][t] = nv;
        __syncthreads();
        src ^= 1;
    }
    int excl = sh[src][t] - v;  // exclusive scan
    if (gi < N_NODES) {
        int o = g_bsum[b] + excl;
        g_off[gi] = o;
        g_cur[gi] = o;
    }
}

__global__ void scatter(const int* __restrict__ ei) {
    int e = blockIdx.x * blockDim.x + threadIdx.x;
    if (e < N_EDGES) {
        int d = ei[N_EDGES + e];
        int p = atomicAdd(&g_cur[d], 1);
        g_srcs[p] = ei[e];
    }
}

// ---------------- aggregation: warp per dst node, zero atomics -------------
__global__ void agg_kernel(const float* __restrict__ h, float* __restrict__ om) {
    int warp = (blockIdx.x * blockDim.x + threadIdx.x) >> 5;
    int lane = threadIdx.x & 31;
    if (warp >= N_NODES) return;
    int j0 = g_off[warp], j1 = g_off[warp + 1];
    float4 den = make_float4(0.f, 0.f, 0.f, 0.f);
    float4 num = make_float4(0.f, 0.f, 0.f, 0.f);
    for (int j = j0; j < j1; j++) {
        int s = g_srcs[j];
        float4 v = __ldg((const float4*)(h + (size_t)s * C) + lane);
        float m0 = v.x + EPS_GEN, m1 = v.y + EPS_GEN;
        float m2 = v.z + EPS_GEN, m3 = v.w + EPS_GEN;
        float e0 = __expf(m0), e1 = __expf(m1);
        float e2 = __expf(m2), e3 = __expf(m3);
        den.x += e0; den.y += e1; den.z += e2; den.w += e3;
        num.x += m0 * e0; num.y += m1 * e1; num.z += m2 * e2; num.w += m3 * e3;
    }
    float4 hd = ((const float4*)(h + (size_t)warp * C))[lane];
    float4 o;
    o.x = num.x / (den.x + 1e-16f) + hd.x;
    o.y = num.y / (den.y + 1e-16f) + hd.y;
    o.z = num.z / (den.z + 1e-16f) + hd.z;
    o.w = num.w / (den.w + 1e-16f) + hd.w;
    ((float4*)(om + (size_t)warp * C))[lane] = o;
}

// ---------------- tf32 tensor-core GEMM, double-buffered -------------------
// C[M,N] = op(A|A2)[M,K] @ B[K,N] + bias
// A supplies k < Ksplit (stride lda, PRE-transform applied), A2 supplies
// k >= Ksplit (stride lda2, raw). PRE: relu(a*scale+shift) on the fly.
// STATS: per-column sum/sumsq of output accumulated for the next BN.
__device__ __forceinline__ unsigned f2tf32(float v) {
    unsigned u;
    asm("cvt.rna.tf32.f32 %0, %1;" : "=r"(u) : "f"(v));
    return u;
}

template <bool PRE, bool STATS>
__global__ __launch_bounds__(256)
void gemm_tc(const float* __restrict__ A, int lda,
             const float* __restrict__ A2, int lda2, int Ksplit,
             const float* __restrict__ B,
             const float* __restrict__ bias,
             float* __restrict__ Cout, int M, int Ncols, int K) {
    __shared__ unsigned As[2][16][136];  // [buf][k][m]
    __shared__ unsigned Bs[2][16][136];  // [buf][k][n]
    __shared__ float smS[128], smQ[128];

    int tid = threadIdx.x;
    int warpId = tid >> 5, lane = tid & 31;
    int grp = lane >> 2, tig = lane & 3;
    int wm = (warpId >> 2) * 64;
    int wn = (warpId & 3) * 32;
    int rowBase = blockIdx.y * 128;
    int colBase = blockIdx.x * 128;

    // A staging: i = tid + s*256 -> m = i>>2, kq = i&3
    int am = (tid + 0) >> 2, akq0 = tid & 3;
    int am1 = (tid + 256) >> 2;                // kq same (tid&3) since 256%4==0
    // B staging: i = tid + s*256 -> k = i>>5, nq = i&31
    int bk0 = tid >> 5, bnq = tid & 31;
    int bk1 = (tid + 256) >> 5;

    float4 va0, va1, vb0, vb1;

    auto ldA = [&](int k0) {
        int kk = k0 + akq0 * 4;
        const float4 z = make_float4(0.f, 0.f, 0.f, 0.f);
        bool second = (A2 != nullptr) && (k0 >= Ksplit);
        if (second) {
            int kr = kk - Ksplit;
            int r0 = rowBase + am, r1 = rowBase + am1;
            va0 = (r0 < M) ? *(const float4*)(A2 + (size_t)r0 * lda2 + kr) : z;
            va1 = (r1 < M) ? *(const float4*)(A2 + (size_t)r1 * lda2 + kr) : z;
        } else {
            int r0 = rowBase + am, r1 = rowBase + am1;
            va0 = (r0 < M) ? *(const float4*)(A + (size_t)r0 * lda + kk) : z;
            va1 = (r1 < M) ? *(const float4*)(A + (size_t)r1 * lda + kk) : z;
        }
    };
    auto stsA = [&](int buf, int k0) {
        int kk = akq0 * 4;
        float4 v0 = va0, v1 = va1;
        if (PRE && k0 < Ksplit) {
            float s0 = g_scale[k0 + kk + 0], h0 = g_shift[k0 + kk + 0];
            float s1 = g_scale[k0 + kk + 1], h1 = g_shift[k0 + kk + 1];
            float s2 = g_scale[k0 + kk + 2], h2 = g_shift[k0 + kk + 2];
            float s3 = g_scale[k0 + kk + 3], h3 = g_shift[k0 + kk + 3];
            v0.x = fmaxf(fmaf(v0.x, s0, h0), 0.f);
            v0.y = fmaxf(fmaf(v0.y, s1, h1), 0.f);
            v0.z = fmaxf(fmaf(v0.z, s2, h2), 0.f);
            v0.w = fmaxf(fmaf(v0.w, s3, h3), 0.f);
            v1.x = fmaxf(fmaf(v1.x, s0, h0), 0.f);
            v1.y = fmaxf(fmaf(v1.y, s1, h1), 0.f);
            v1.z = fmaxf(fmaf(v1.z, s2, h2), 0.f);
            v1.w = fmaxf(fmaf(v1.w, s3, h3), 0.f);
        }
        As[buf][kk + 0][am]  = f2tf32(v0.x);
        As[buf][kk + 1][am]  = f2tf32(v0.y);
        As[buf][kk + 2][am]  = f2tf32(v0.z);
        As[buf][kk + 3][am]  = f2tf32(v0.w);
        As[buf][kk + 0][am1] = f2tf32(v1.x);
        As[buf][kk + 1][am1] = f2tf32(v1.y);
        As[buf][kk + 2][am1] = f2tf32(v1.z);
        As[buf][kk + 3][am1] = f2tf32(v1.w);
    };
    auto ldB = [&](int k0) {
        vb0 = *(const float4*)(B + (size_t)(k0 + bk0) * Ncols + colBase + bnq * 4);
        vb1 = *(const float4*)(B + (size_t)(k0 + bk1) * Ncols + colBase + bnq * 4);
    };
    auto stsB = [&](int buf) {
        Bs[buf][bk0][bnq * 4 + 0] = f2tf32(vb0.x);
        Bs[buf][bk0][bnq * 4 + 1] = f2tf32(vb0.y);
        Bs[buf][bk0][bnq * 4 + 2] = f2tf32(vb0.z);
        Bs[buf][bk0][bnq * 4 + 3] = f2tf32(vb0.w);
        Bs[buf][bk1][bnq * 4 + 0] = f2tf32(vb1.x);
        Bs[buf][bk1][bnq * 4 + 1] = f2tf32(vb1.y);
        Bs[buf][bk1][bnq * 4 + 2] = f2tf32(vb1.z);
        Bs[buf][bk1][bnq * 4 + 3] = f2tf32(vb1.w);
    };

    float acc[4][4][4];
#pragma unroll
    for (int i = 0; i < 4; i++)
#pragma unroll
        for (int j = 0; j < 4; j++)
#pragma unroll
            for (int r = 0; r < 4; r++) acc[i][j][r] = 0.f;

    ldA(0); ldB(0);
    stsA(0, 0); stsB(0);
    __syncthreads();

    int nt = K / 16;
    for (int kt = 0; kt < nt; kt++) {
        int buf = kt & 1;
        bool more = (kt + 1 < nt);
        if (more) { ldA((kt + 1) * 16); ldB((kt + 1) * 16); }

#pragma unroll
        for (int ks = 0; ks < 16; ks += 8) {
            unsigned a[4][4], b[4][2];
#pragma unroll
            for (int i = 0; i < 4; i++) {
                int r0 = wm + 16 * i + grp;
                a[i][0] = As[buf][ks + tig][r0];
                a[i][1] = As[buf][ks + tig][r0 + 8];
                a[i][2] = As[buf][ks + tig + 4][r0];
                a[i][3] = As[buf][ks + tig + 4][r0 + 8];
            }
#pragma unroll
            for (int j = 0; j < 4; j++) {
                int cn = wn + 8 * j + grp;
                b[j][0] = Bs[buf][ks + tig][cn];
                b[j][1] = Bs[buf][ks + tig + 4][cn];
            }
#pragma unroll
            for (int i = 0; i < 4; i++)
#pragma unroll
                for (int j = 0; j < 4; j++)
                    asm volatile(
                        "mma.sync.aligned.m16n8k8.row.col.f32.tf32.tf32.f32 "
                        "{%0,%1,%2,%3}, {%4,%5,%6,%7}, {%8,%9}, {%0,%1,%2,%3};"
                        : "+f"(acc[i][j][0]), "+f"(acc[i][j][1]),
                          "+f"(acc[i][j][2]), "+f"(acc[i][j][3])
                        : "r"(a[i][0]), "r"(a[i][1]), "r"(a[i][2]), "r"(a[i][3]),
                          "r"(b[j][0]), "r"(b[j][1]));
        }

        if (more) {
            stsA(buf ^ 1, (kt + 1) * 16);
            stsB(buf ^ 1);
            __syncthreads();
        }
    }

    if (STATS) {
        __syncthreads();
        if (tid < 128) { smS[tid] = 0.f; smQ[tid] = 0.f; }
        __syncthreads();
    }

#pragma unroll
    for (int j = 0; j < 4; j++) {
        int colL = wn + 8 * j + 2 * tig;
        int col = colBase + colL;
        float b0 = bias[col], b1 = bias[col + 1];
        float s0 = 0.f, q0 = 0.f, s1 = 0.f, q1 = 0.f;
#pragma unroll
        for (int i = 0; i < 4; i++) {
            int r0 = rowBase + wm + 16 * i + grp;
            int r1 = r0 + 8;
            if (r0 < M) {
                float v0 = acc[i][j][0] + b0;
                float v1 = acc[i][j][1] + b1;
                *(float2*)(Cout + (size_t)r0 * Ncols + col) = make_float2(v0, v1);
                s0 += v0; q0 += v0 * v0; s1 += v1; q1 += v1 * v1;
            }
            if (r1 < M) {
                float v0 = acc[i][j][2] + b0;
                float v1 = acc[i][j][3] + b1;
                *(float2*)(Cout + (size_t)r1 * Ncols + col) = make_float2(v0, v1);
                s0 += v0; q0 += v0 * v0; s1 += v1; q1 += v1 * v1;
            }
        }
        if (STATS) {
            atomicAdd(&smS[colL], s0);
            atomicAdd(&smQ[colL], q0);
            atomicAdd(&smS[colL + 1], s1);
            atomicAdd(&smQ[colL + 1], q1);
        }
    }
    if (STATS) {
        __syncthreads();
        if (tid < 128) {
            atomicAdd(&g_sum[colBase + tid], smS[tid]);
            atomicAdd(&g_sumsq[colBase + tid], smQ[tid]);
        }
    }
}

// ---------------- launch ----------------------------------------------------
extern "C" void kernel_launch(void* const* d_in, const int* in_sizes, int n_in,
                              void* d_out, int out_size) {
    const float* x    = (const float*)d_in[0];
    const int*   ei   = (const int*)d_in[1];   // int32 (JAX x64 disabled)
    const float* bn_g = (const float*)d_in[2];
    const float* bn_b = (const float*)d_in[3];
    const float* W1   = (const float*)d_in[4];
    const float* b1   = (const float*)d_in[5];
    const float* g1   = (const float*)d_in[6];
    const float* be1  = (const float*)d_in[7];
    const float* W2   = (const float*)d_in[8];
    const float* b2   = (const float*)d_in[9];
    const float* g2   = (const float*)d_in[10];
    const float* be2  = (const float*)d_in[11];
    const float* W3   = (const float*)d_in[12];
    const float* b3   = (const float*)d_in[13];
    const float* We   = (const float*)d_in[14];
    const float* be   = (const float*)d_in[15];
    float* out = (float*)d_out;

    float* p_h;   cudaGetSymbolAddress((void**)&p_h,   g_h);
    float* p_min; cudaGetSymbolAddress((void**)&p_min, g_min);
    float* p_y0;  cudaGetSymbolAddress((void**)&p_y0,  g_y0);
    float* p_y1;  cudaGetSymbolAddress((void**)&p_y1,  g_y1);
    float* p_wc;  cudaGetSymbolAddress((void**)&p_wc,  g_wc);
    float* p_bc;  cudaGetSymbolAddress((void**)&p_bc,  g_bc);

    const int EW = 256;
    int nNC = N_NODES * C;
    dim3 gemmGridH(2, (N_NODES + 127) / 128);   // N = 256
    dim3 gemmGridC(1, (N_NODES + 127) / 128);   // N = 128

    // --- BN(x) -> h ---
    zero_stats<<<1, H>>>();
    colstats<<<512, C>>>(x, N_NODES, C);
    finalize_stats<<<1, C>>>(C, N_NODES, bn_g, bn_b);
    bn_relu4<<<(nNC / 4 + EW - 1) / EW, EW>>>(x, p_h, nNC / 4, C / 4 - 1);

    // --- combined layer3+encoder weights (independent; overlap-friendly) ---
    build_wc<<<256, 128>>>(W3, We);
    cudaMemcpyAsync(p_wc + 256 * 128, We, 128 * 128 * sizeof(float),
                    cudaMemcpyDeviceToDevice);
    build_bc<<<1, 128>>>(b3, We, be);

    // --- build dst-CSR (counting sort) ---
    zero_cnt<<<(N_NODES + EW - 1) / EW, EW>>>();
    hist<<<(N_EDGES + EW - 1) / EW, EW>>>(ei);
    scan_sums<<<NSCAN, SCAN_B>>>();
    scan_bsum<<<1, 128>>>();
    scan_final<<<NSCAN, SCAN_B>>>();
    scatter<<<(N_EDGES + EW - 1) / EW, EW>>>(ei);

    // --- softmax aggregation + root add (warp per node) ---
    agg_kernel<<<N_NODES / 8, 256>>>(p_h, p_min);

    // --- MLP layer 1: y0 = mlp_in @ W1 + b1 (stats fused) ---
    zero_stats<<<1, H>>>();
    gemm_tc<false, true><<<gemmGridH, 256>>>(
        p_min, C, nullptr, 0, C, W1, b1, p_y0, N_NODES, H, C);
    finalize_stats<<<1, H>>>(H, N_NODES, g1, be1);

    // --- MLP layer 2: y1 = relu(BN(y0)) @ W2 + b2 (pre + stats fused) ---
    zero_stats<<<1, H>>>();
    gemm_tc<true, true><<<gemmGridH, 256>>>(
        p_y0, H, nullptr, 0, H, W2, b2, p_y1, N_NODES, H, H);
    finalize_stats<<<1, H>>>(H, N_NODES, g2, be2);

    // --- fused layer3+encoder: out = [relu(BN(y1)) | x] @ Wc + bc ---
    gemm_tc<true, false><<<gemmGridC, 256>>>(
        p_y1, H, x, C, H, p_wc, p_bc, out, N_NODES, C, H + C);
}